// round 2
// baseline (speedup 1.0000x reference)
#include <cuda_runtime.h>
#include <stdint.h>

#define LL 4
#define BB 4
#define HH 4096
#define NKV 8
#define HD 128
#define SS 1024

// per-tensor output element count: L*B*NKV*(S+1)*HD
static const long long TEN = (long long)LL * BB * NKV * (SS + 1) * HD;   // 16,793,600
static const long long TEN_F4 = TEN / 4;                                  // 4,198,400
static const long long PAST_F4 = (long long)LL * BB * NKV * SS * HD / 4;  // 4,194,304 per tensor

// ---------------------------------------------------------------------------
// Projection + RoPE + write new KV row at seq index S.
// One warp computes an adjacent output pair (o_even, o_odd) for ALL B batches,
// so each weight element is read exactly once. Hidden (B x H = 64KB) lives in
// dynamic shared memory, loaded once per block.
// Grid: 512 blocks x 256 threads (8 warps) -> 4096 warps = L*2*512 pairs.
// ---------------------------------------------------------------------------
__global__ void kv_proj_kernel(const int* __restrict__ token_id,
                               const int* __restrict__ pos_id,
                               const float* __restrict__ embed_w,
                               const float* __restrict__ wk,
                               const float* __restrict__ wv,
                               const float* __restrict__ inv_freq,
                               float* __restrict__ out) {
    extern __shared__ float4 sh[];  // B * H/4 float4 = 4096 float4 = 64KB

    const int tid = threadIdx.x;

    // Stage hidden = embed_w[token_id[b]] for all batches into smem.
    for (int i = tid; i < BB * (HH / 4); i += blockDim.x) {
        int b  = i >> 10;            // / (H/4)
        int h4 = i & 1023;           // % (H/4)
        long long tok = token_id[b];
        sh[i] = reinterpret_cast<const float4*>(embed_w + tok * HH)[h4];
    }
    __syncthreads();

    const int warp = tid >> 5;
    const int lane = tid & 31;
    const int gwarp = blockIdx.x * 8 + warp;       // 0..4095
    const int l   = gwarp >> 10;                   // layer
    const int rem = gwarp & 1023;
    const int kv  = rem >> 9;                      // 0 = k, 1 = v
    const int p   = rem & 511;                     // pair index within (l, kv)
    const int o_e = 2 * p;                         // even output dim (0..1022)

    const float* wbase = (kv == 0 ? wk : wv);
    const float4* we = reinterpret_cast<const float4*>(
        wbase + ((long long)l * (NKV * HD) + o_e) * HH);
    const float4* wo = reinterpret_cast<const float4*>(
        wbase + ((long long)l * (NKV * HD) + o_e + 1) * HH);

    float acc_e[BB] = {0.f, 0.f, 0.f, 0.f};
    float acc_o[BB] = {0.f, 0.f, 0.f, 0.f};

    #pragma unroll 4
    for (int i = lane; i < HH / 4; i += 32) {
        float4 a = we[i];
        float4 c = wo[i];
        #pragma unroll
        for (int b = 0; b < BB; b++) {
            float4 hv = sh[b * (HH / 4) + i];
            acc_e[b] += a.x * hv.x + a.y * hv.y + a.z * hv.z + a.w * hv.w;
            acc_o[b] += c.x * hv.x + c.y * hv.y + c.z * hv.z + c.w * hv.w;
        }
    }

    // Warp reduction of all 8 accumulators.
    #pragma unroll
    for (int off = 16; off > 0; off >>= 1) {
        #pragma unroll
        for (int b = 0; b < BB; b++) {
            acc_e[b] += __shfl_down_sync(0xffffffffu, acc_e[b], off);
            acc_o[b] += __shfl_down_sync(0xffffffffu, acc_o[b], off);
        }
    }

    if (lane == 0) {
        const int n  = o_e / HD;            // kv head
        const int i2 = (o_e % HD) >> 1;     // rope pair index within head
        const long long base_t = (kv == 0) ? 0LL : TEN;
        const float f = inv_freq[l * (HD / 2) + i2];
        #pragma unroll
        for (int b = 0; b < BB; b++) {
            float e = acc_e[b];
            float o = acc_o[b];
            float re = e, ro = o;
            if (kv == 0) {
                float ang = (float)pos_id[b] * f;
                float s, c;
                sincosf(ang, &s, &c);
                re = e * c - o * s;
                ro = e * s + o * c;
            }
            long long dst = base_t +
                ((((long long)l * BB + b) * NKV + n) * (SS + 1) + SS) * HD + 2 * i2;
            out[dst]     = re;
            out[dst + 1] = ro;
        }
    }
}

// ---------------------------------------------------------------------------
// Concat copy: past_{k,v} -> out rows [0, S) of each (l,b,n) group.
// Group = S*HD floats contiguous in src; dst groups stride by (S+1)*HD.
// float4-vectorized grid-stride loop.
// ---------------------------------------------------------------------------
__global__ void kv_copy_kernel(const float4* __restrict__ past_k,
                               const float4* __restrict__ past_v,
                               float4* __restrict__ out) {
    const long long total  = 2 * PAST_F4;       // 8,388,608 float4
    const long long dstG   = (SS + 1) * HD / 4; // 32800
    long long idx    = (long long)blockIdx.x * blockDim.x + threadIdx.x;
    long long stride = (long long)gridDim.x * blockDim.x;

    for (; idx < total; idx += stride) {
        int       t = (idx >= PAST_F4);
        long long j = idx - (t ? PAST_F4 : 0);
        long long g = j >> 15;          // / 32768 (group index, 0..127)
        long long w = j & 32767;        // within-group float4 offset
        const float4* src = t ? past_v : past_k;
        out[(long long)t * TEN_F4 + g * dstG + w] = src[j];
    }
}

extern "C" void kernel_launch(void* const* d_in, const int* in_sizes, int n_in,
                              void* d_out, int out_size) {
    const int*   token_id = (const int*)d_in[0];
    const int*   pos_id   = (const int*)d_in[1];
    const float* embed_w  = (const float*)d_in[2];
    // d_in[3] = wq  (unused: q is computed but never returned by the reference)
    const float* wk       = (const float*)d_in[4];
    const float* wv       = (const float*)d_in[5];
    const float* inv_freq = (const float*)d_in[6];
    const float* past_k   = (const float*)d_in[7];
    const float* past_v   = (const float*)d_in[8];
    float*       out      = (float*)d_out;

    // 64KB dynamic smem needs an explicit opt-in (static limit is 48KB).
    cudaFuncSetAttribute(kv_proj_kernel,
                         cudaFuncAttributeMaxDynamicSharedMemorySize, 65536);

    kv_proj_kernel<<<512, 256, 65536>>>(token_id, pos_id, embed_w,
                                        wk, wv, inv_freq, out);

    kv_copy_kernel<<<8192, 256>>>((const float4*)past_k, (const float4*)past_v,
                                  (float4*)out);
}

// round 5
// speedup vs baseline: 1.3536x; 1.3536x over previous
#include <cuda_runtime.h>
#include <stdint.h>

#define LL 4
#define BB 4
#define HH 4096
#define NKVH 8
#define HD 128
#define SS 1024

static const long long TEN    = (long long)LL * BB * NKVH * (SS + 1) * HD;  // 16,793,600
static const long long TEN_F4 = TEN / 4;                                    // 4,198,400

// ---------------------------------------------------------------------------
// Projection + RoPE + write new KV row at seq index S.
// 128 blocks x 512 threads = 2048 warps, ONE wave on 148 SMs.
// Each warp computes 4 consecutive output rows (2 rope pairs) for all 4
// batches: 16 accumulators, 4 LDG.128 + 4 LDS.128 per iteration, 32 iters.
// Hidden (B x H = 64KB) staged in dynamic smem once per block.
// ---------------------------------------------------------------------------
__global__ void __launch_bounds__(512, 1)
kv_proj_kernel(const int* __restrict__ token_id,
               const int* __restrict__ pos_id,
               const float* __restrict__ embed_w,
               const float* __restrict__ wk,
               const float* __restrict__ wv,
               const float* __restrict__ inv_freq,
               float* __restrict__ out) {
    extern __shared__ float4 sh[];  // 4096 float4 = 64KB

    const int tid = threadIdx.x;

    // Stage hidden rows for all 4 batches (tokens cached in L2 after block 0).
    #pragma unroll
    for (int it = 0; it < 8; it++) {
        int i  = tid + it * 512;             // 0..4095
        int b  = i >> 10;
        int h4 = i & 1023;
        long long tok = token_id[b];
        sh[i] = reinterpret_cast<const float4*>(embed_w + tok * HH)[h4];
    }
    __syncthreads();

    const int warp  = tid >> 5;
    const int lane  = tid & 31;
    const int gwarp = blockIdx.x * 16 + warp;   // 0..2047
    const int lkv   = gwarp >> 8;               // 0..7
    const int l     = lkv >> 1;
    const int kv    = lkv & 1;                  // 0 = k, 1 = v
    const int r0    = (gwarp & 255) * 4;        // first of 4 rows (mult of 4)

    const float* wbase = (kv == 0 ? wk : wv);
    const float4* w0 = reinterpret_cast<const float4*>(
        wbase + ((long long)l * (NKVH * HD) + r0) * HH);
    const float4* w1 = w0 + (HH / 4);
    const float4* w2 = w1 + (HH / 4);
    const float4* w3 = w2 + (HH / 4);

    float acc[4][BB];
    #pragma unroll
    for (int r = 0; r < 4; r++)
        #pragma unroll
        for (int b = 0; b < BB; b++) acc[r][b] = 0.f;

    #pragma unroll 2
    for (int i = lane; i < HH / 4; i += 32) {
        float4 a0 = w0[i];
        float4 a1 = w1[i];
        float4 a2 = w2[i];
        float4 a3 = w3[i];
        #pragma unroll
        for (int b = 0; b < BB; b++) {
            float4 hv = sh[b * (HH / 4) + i];
            acc[0][b] += a0.x * hv.x + a0.y * hv.y + a0.z * hv.z + a0.w * hv.w;
            acc[1][b] += a1.x * hv.x + a1.y * hv.y + a1.z * hv.z + a1.w * hv.w;
            acc[2][b] += a2.x * hv.x + a2.y * hv.y + a2.z * hv.z + a2.w * hv.w;
            acc[3][b] += a3.x * hv.x + a3.y * hv.y + a3.z * hv.z + a3.w * hv.w;
        }
    }

    #pragma unroll
    for (int off = 16; off > 0; off >>= 1)
        #pragma unroll
        for (int r = 0; r < 4; r++)
            #pragma unroll
            for (int b = 0; b < BB; b++)
                acc[r][b] += __shfl_down_sync(0xffffffffu, acc[r][b], off);

    if (lane == 0) {
        const int n  = r0 >> 7;             // kv head
        const int m0 = (r0 & 127) >> 1;     // first rope-pair index
        const long long base_t = (kv == 0) ? 0LL : TEN;
        #pragma unroll
        for (int p = 0; p < 2; p++) {
            const float f = inv_freq[l * (HD / 2) + m0 + p];
            #pragma unroll
            for (int b = 0; b < BB; b++) {
                float e = acc[2 * p][b];
                float o = acc[2 * p + 1][b];
                float re = e, ro = o;
                if (kv == 0) {
                    float ang = (float)pos_id[b] * f;
                    float s, c;
                    sincosf(ang, &s, &c);
                    re = e * c - o * s;
                    ro = e * s + o * c;
                }
                long long dst = base_t +
                    ((((long long)l * BB + b) * NKVH + n) * (SS + 1) + SS) * HD
                    + 2 * (m0 + p);
                out[dst]     = re;
                out[dst + 1] = ro;
            }
        }
    }
}

// ---------------------------------------------------------------------------
// Concat copy: past_{k,v} -> out rows [0, S) of each (l,b,n) group.
// src group = 32768 float4 contiguous; dst index = j + (j>>15)*32.
// No loop: 4 batched coalesced loads, then 4 stores. Tensor picked by block.
// Grid: 8192 blocks x 256 threads (blocks [0,4096) = k, [4096,8192) = v).
// ---------------------------------------------------------------------------
__global__ void __launch_bounds__(256)
kv_copy_kernel(const float4* __restrict__ past_k,
               const float4* __restrict__ past_v,
               float4* __restrict__ out) {
    const int  t   = blockIdx.x >> 12;                  // 0 = k, 1 = v
    const float4* __restrict__ src = t ? past_v : past_k;
    float4* __restrict__ dst = out + (long long)t * TEN_F4;

    const long long T  = 4096LL * 256;                  // threads per tensor
    long long tid = (long long)(blockIdx.x & 4095) * 256 + threadIdx.x;

    long long j0 = tid;
    long long j1 = tid + T;
    long long j2 = tid + 2 * T;
    long long j3 = tid + 3 * T;

    float4 v0 = src[j0];
    float4 v1 = src[j1];
    float4 v2 = src[j2];
    float4 v3 = src[j3];

    dst[j0 + ((j0 >> 15) << 5)] = v0;
    dst[j1 + ((j1 >> 15) << 5)] = v1;
    dst[j2 + ((j2 >> 15) << 5)] = v2;
    dst[j3 + ((j3 >> 15) << 5)] = v3;
}

extern "C" void kernel_launch(void* const* d_in, const int* in_sizes, int n_in,
                              void* d_out, int out_size) {
    const int*   token_id = (const int*)d_in[0];
    const int*   pos_id   = (const int*)d_in[1];
    const float* embed_w  = (const float*)d_in[2];
    // d_in[3] = wq (unused: q never escapes the reference)
    const float* wk       = (const float*)d_in[4];
    const float* wv       = (const float*)d_in[5];
    const float* inv_freq = (const float*)d_in[6];
    const float* past_k   = (const float*)d_in[7];
    const float* past_v   = (const float*)d_in[8];
    float*       out      = (float*)d_out;

    cudaFuncSetAttribute(kv_proj_kernel,
                         cudaFuncAttributeMaxDynamicSharedMemorySize, 65536);

    kv_proj_kernel<<<128, 512, 65536>>>(token_id, pos_id, embed_w,
                                        wk, wv, inv_freq, out);

    kv_copy_kernel<<<8192, 256>>>((const float4*)past_k, (const float4*)past_v,
                                  (float4*)out);
}

// round 6
// speedup vs baseline: 1.3897x; 1.0267x over previous
#include <cuda_runtime.h>
#include <stdint.h>

#define LL 4
#define BB 4
#define HH 4096
#define NKVH 8
#define HD 128
#define SS 1024

static const long long TEN     = (long long)LL * BB * NKVH * (SS + 1) * HD; // 16,793,600
static const long long TEN_F4  = TEN / 4;                                   // 4,198,400
static const long long PAST_F4 = 1LL << 22;   // per-tensor past float4 count (4,194,304)
static const long long TOT_F4  = 1LL << 23;   // both tensors

#define PROJ_BLOCKS 128
#define COPY_BLOCKS 168
#define NBLOCKS     (PROJ_BLOCKS + COPY_BLOCKS)   // 296 = 2 per SM, one wave
#define NTHREADS    512

// ---------------------------------------------------------------------------
// Fused kernel.
//  Blocks [0,128):  GEMV (k,v projections) + RoPE -> new row at seq index S.
//     Each of the 2048 warps computes 4 consecutive output rows x 4 batches.
//     Hidden (B x H = 64KB) staged in dynamic smem once per block.
//  Blocks [128,296): concat copy past_{k,v} -> out rows [0,S), strided groups.
//     Grid-stride with 4 batched float4 loads per iteration (MLP=4).
//  Running both concurrently makes DRAM the single shared bottleneck.
// ---------------------------------------------------------------------------
__global__ void __launch_bounds__(NTHREADS, 2)
kv_fused_kernel(const int* __restrict__ token_id,
                const int* __restrict__ pos_id,
                const float* __restrict__ embed_w,
                const float* __restrict__ wk,
                const float* __restrict__ wv,
                const float* __restrict__ inv_freq,
                const float4* __restrict__ past_k,
                const float4* __restrict__ past_v,
                float* __restrict__ out) {
    const int tid = threadIdx.x;

    if (blockIdx.x >= PROJ_BLOCKS) {
        // ---------------- copy path ----------------
        float4* __restrict__ o4 = reinterpret_cast<float4*>(out);
        const long long CT   = (long long)COPY_BLOCKS * NTHREADS;     // 86016
        long long ctid = (long long)(blockIdx.x - PROJ_BLOCKS) * NTHREADS + tid;

        long long idx = ctid;
        // full batches of 4 (96 strides cover 8,257,536 of 8,388,608)
        for (; idx + 3 * CT < TOT_F4; idx += 4 * CT) {
            long long i0 = idx, i1 = idx + CT, i2 = idx + 2 * CT, i3 = idx + 3 * CT;
            float4 v0 = (i0 >> 22) ? past_v[i0 & (PAST_F4 - 1)] : past_k[i0];
            float4 v1 = (i1 >> 22) ? past_v[i1 & (PAST_F4 - 1)] : past_k[i1];
            float4 v2 = (i2 >> 22) ? past_v[i2 & (PAST_F4 - 1)] : past_k[i2];
            float4 v3 = (i3 >> 22) ? past_v[i3 & (PAST_F4 - 1)] : past_k[i3];
            long long j0 = i0 & (PAST_F4 - 1), j1 = i1 & (PAST_F4 - 1);
            long long j2 = i2 & (PAST_F4 - 1), j3 = i3 & (PAST_F4 - 1);
            o4[(i0 >> 22) * TEN_F4 + j0 + ((j0 >> 15) << 5)] = v0;
            o4[(i1 >> 22) * TEN_F4 + j1 + ((j1 >> 15) << 5)] = v1;
            o4[(i2 >> 22) * TEN_F4 + j2 + ((j2 >> 15) << 5)] = v2;
            o4[(i3 >> 22) * TEN_F4 + j3 + ((j3 >> 15) << 5)] = v3;
        }
        // tail
        for (; idx < TOT_F4; idx += CT) {
            long long t = idx >> 22;
            long long j = idx & (PAST_F4 - 1);
            float4 v = t ? past_v[j] : past_k[j];
            o4[t * TEN_F4 + j + ((j >> 15) << 5)] = v;
        }
        return;
    }

    // ---------------- projection path ----------------
    extern __shared__ float4 sh[];  // 4096 float4 = 64KB

    #pragma unroll
    for (int it = 0; it < 8; it++) {
        int i  = tid + it * NTHREADS;        // 0..4095
        int b  = i >> 10;
        int h4 = i & 1023;
        long long tok = token_id[b];
        sh[i] = reinterpret_cast<const float4*>(embed_w + tok * HH)[h4];
    }
    __syncthreads();

    const int warp  = tid >> 5;
    const int lane  = tid & 31;
    const int gwarp = blockIdx.x * 16 + warp;   // 0..2047
    const int lkv   = gwarp >> 8;               // 0..7
    const int l     = lkv >> 1;
    const int kv    = lkv & 1;                  // 0 = k, 1 = v
    const int r0    = (gwarp & 255) * 4;        // first of 4 rows

    const float* wbase = (kv == 0 ? wk : wv);
    const float4* w0 = reinterpret_cast<const float4*>(
        wbase + ((long long)l * (NKVH * HD) + r0) * HH);
    const float4* w1 = w0 + (HH / 4);
    const float4* w2 = w1 + (HH / 4);
    const float4* w3 = w2 + (HH / 4);

    float acc[4][BB];
    #pragma unroll
    for (int r = 0; r < 4; r++)
        #pragma unroll
        for (int b = 0; b < BB; b++) acc[r][b] = 0.f;

    #pragma unroll 2
    for (int i = lane; i < HH / 4; i += 32) {
        float4 a0 = w0[i];
        float4 a1 = w1[i];
        float4 a2 = w2[i];
        float4 a3 = w3[i];
        #pragma unroll
        for (int b = 0; b < BB; b++) {
            float4 hv = sh[b * (HH / 4) + i];
            acc[0][b] += a0.x * hv.x + a0.y * hv.y + a0.z * hv.z + a0.w * hv.w;
            acc[1][b] += a1.x * hv.x + a1.y * hv.y + a1.z * hv.z + a1.w * hv.w;
            acc[2][b] += a2.x * hv.x + a2.y * hv.y + a2.z * hv.z + a2.w * hv.w;
            acc[3][b] += a3.x * hv.x + a3.y * hv.y + a3.z * hv.z + a3.w * hv.w;
        }
    }

    #pragma unroll
    for (int off = 16; off > 0; off >>= 1)
        #pragma unroll
        for (int r = 0; r < 4; r++)
            #pragma unroll
            for (int b = 0; b < BB; b++)
                acc[r][b] += __shfl_down_sync(0xffffffffu, acc[r][b], off);

    if (lane == 0) {
        const int n  = r0 >> 7;             // kv head
        const int m0 = (r0 & 127) >> 1;     // first rope-pair index
        const long long base_t = (kv == 0) ? 0LL : TEN;
        #pragma unroll
        for (int p = 0; p < 2; p++) {
            const float f = inv_freq[l * (HD / 2) + m0 + p];
            #pragma unroll
            for (int b = 0; b < BB; b++) {
                float e = acc[2 * p][b];
                float o = acc[2 * p + 1][b];
                float re = e, ro = o;
                if (kv == 0) {
                    float ang = (float)pos_id[b] * f;
                    float s, c;
                    sincosf(ang, &s, &c);
                    re = e * c - o * s;
                    ro = e * s + o * c;
                }
                long long dst = base_t +
                    ((((long long)l * BB + b) * NKVH + n) * (SS + 1) + SS) * HD
                    + 2 * (m0 + p);
                out[dst]     = re;
                out[dst + 1] = ro;
            }
        }
    }
}

extern "C" void kernel_launch(void* const* d_in, const int* in_sizes, int n_in,
                              void* d_out, int out_size) {
    const int*   token_id = (const int*)d_in[0];
    const int*   pos_id   = (const int*)d_in[1];
    const float* embed_w  = (const float*)d_in[2];
    // d_in[3] = wq (unused: q never escapes the reference)
    const float* wk       = (const float*)d_in[4];
    const float* wv       = (const float*)d_in[5];
    const float* inv_freq = (const float*)d_in[6];
    const float* past_k   = (const float*)d_in[7];
    const float* past_v   = (const float*)d_in[8];
    float*       out      = (float*)d_out;

    cudaFuncSetAttribute(kv_fused_kernel,
                         cudaFuncAttributeMaxDynamicSharedMemorySize, 65536);

    kv_fused_kernel<<<NBLOCKS, NTHREADS, 65536>>>(
        token_id, pos_id, embed_w, wk, wv, inv_freq,
        (const float4*)past_k, (const float4*)past_v, out);
}

// round 7
// speedup vs baseline: 1.4035x; 1.0099x over previous
#include <cuda_runtime.h>
#include <stdint.h>

#define LL 4
#define BB 4
#define HH 4096
#define NKVH 8
#define HD 128
#define SS 1024

static const long long TEN     = (long long)LL * BB * NKVH * (SS + 1) * HD; // 16,793,600
static const long long TEN_F4  = TEN / 4;                                   // 4,198,400
static const long long PAST_F4 = 1LL << 22;   // per-tensor past float4 count
static const long long TOT_F4  = 1LL << 23;   // both tensors

#define PROJ_BLOCKS 128
#define COPY_BLOCKS 168
#define NBLOCKS     (PROJ_BLOCKS + COPY_BLOCKS)   // 296 = 2/SM, one wave
#define NTHREADS    512

// ---- packed f32x2 helpers (sm_100+; ptxas won't auto-fuse these) ----------
__device__ __forceinline__ void fma2(unsigned long long& acc,
                                     unsigned long long ab,
                                     unsigned long long hv) {
    asm("fma.rn.f32x2 %0, %1, %2, %0;" : "+l"(acc) : "l"(ab), "l"(hv));
}
__device__ __forceinline__ unsigned long long pack2(float w) {
    unsigned long long r;
    asm("mov.b64 %0, {%1, %1};" : "=l"(r) : "f"(w));
    return r;
}
__device__ __forceinline__ void unpack2(unsigned long long v, float& lo, float& hi) {
    asm("mov.b64 {%0, %1}, %2;" : "=f"(lo), "=f"(hi) : "l"(v));
}

// ---------------------------------------------------------------------------
// Fused kernel.
//  Blocks [0,128):  GEMV (k,v) + RoPE -> new row at seq index S.
//     Hidden staged in smem batch-interleaved: sh[0][i]=(b0,b1 @pos 4i,4i+1),
//     sh[1][i]=(b0,b1 @4i+2,4i+3), sh[2..3] same for (b2,b3). 16B/lane stride
//     -> conflict-free LDS.128. Inner loop: 4 LDG.128 + 4 LDS.128 + 32 FMA2.
//  Blocks [128,296): concat copy, 8 batched loads then 8 stores per iter.
// ---------------------------------------------------------------------------
__global__ void __launch_bounds__(NTHREADS, 2)
kv_fused_kernel(const int* __restrict__ token_id,
                const int* __restrict__ pos_id,
                const float* __restrict__ embed_w,
                const float* __restrict__ wk,
                const float* __restrict__ wv,
                const float* __restrict__ inv_freq,
                const float4* __restrict__ past_k,
                const float4* __restrict__ past_v,
                float* __restrict__ out) {
    const int tid = threadIdx.x;

    if (blockIdx.x >= PROJ_BLOCKS) {
        // ---------------- copy path ----------------
        float4* __restrict__ o4 = reinterpret_cast<float4*>(out);
        const long long CT = (long long)COPY_BLOCKS * NTHREADS;   // 86016
        long long ctid = (long long)(blockIdx.x - PROJ_BLOCKS) * NTHREADS + tid;

        long long idx = ctid;
        for (; idx + 7 * CT < TOT_F4; idx += 8 * CT) {
            float4 v[8];
            long long j[8];
            long long t[8];
            #pragma unroll
            for (int u = 0; u < 8; u++) {
                long long i = idx + u * CT;
                t[u] = i >> 22;
                j[u] = i & (PAST_F4 - 1);
                v[u] = t[u] ? past_v[j[u]] : past_k[j[u]];
            }
            #pragma unroll
            for (int u = 0; u < 8; u++)
                o4[t[u] * TEN_F4 + j[u] + ((j[u] >> 15) << 5)] = v[u];
        }
        for (; idx < TOT_F4; idx += CT) {
            long long t = idx >> 22;
            long long j = idx & (PAST_F4 - 1);
            float4 v = t ? past_v[j] : past_k[j];
            o4[t * TEN_F4 + j + ((j >> 15) << 5)] = v;
        }
        return;
    }

    // ---------------- projection path ----------------
    extern __shared__ float4 sh[];  // 4 arrays x 1024 float4 = 64KB
    // sh[a*1024 + i]: a=0 -> (b0,b1)@(4i,4i+1); a=1 -> (b0,b1)@(4i+2,4i+3);
    //                 a=2 -> (b2,b3)@(4i,4i+1); a=3 -> (b2,b3)@(4i+2,4i+3)

    {
        long long tk0 = token_id[0], tk1 = token_id[1];
        long long tk2 = token_id[2], tk3 = token_id[3];
        const float* e0 = embed_w + tk0 * HH;
        const float* e1 = embed_w + tk1 * HH;
        const float* e2 = embed_w + tk2 * HH;
        const float* e3 = embed_w + tk3 * HH;
        #pragma unroll
        for (int it = 0; it < 8; it++) {
            int e  = tid + it * NTHREADS;        // 0..4095
            int a  = e >> 10;                    // which array
            int i  = e & 1023;
            int p0 = 4 * i + 2 * (a & 1);        // first position of the pair
            const float* ea = (a < 2) ? e0 : e2;
            const float* eb = (a < 2) ? e1 : e3;
            float2 x = *reinterpret_cast<const float2*>(ea + p0);
            float2 y = *reinterpret_cast<const float2*>(eb + p0);
            sh[e] = make_float4(x.x, y.x, x.y, y.y);
        }
    }
    __syncthreads();

    const int warp  = tid >> 5;
    const int lane  = tid & 31;
    const int gwarp = blockIdx.x * 16 + warp;   // 0..2047
    const int lkv   = gwarp >> 8;               // 0..7
    const int l     = lkv >> 1;
    const int kv    = lkv & 1;                  // 0 = k, 1 = v
    const int r0    = (gwarp & 255) * 4;        // first of 4 rows

    const float* wbase = (kv == 0 ? wk : wv);
    const float4* wb4 = reinterpret_cast<const float4*>(
        wbase + ((long long)l * (NKVH * HD) + r0) * HH);
    const ulonglong2* shp = reinterpret_cast<const ulonglong2*>(sh);

    unsigned long long acc01[4], acc23[4];
    #pragma unroll
    for (int r = 0; r < 4; r++) { acc01[r] = 0ull; acc23[r] = 0ull; }

    #pragma unroll 2
    for (int i = lane; i < HH / 4; i += 32) {
        float4 w0 = wb4[i];
        float4 w1 = wb4[i + 1024];
        float4 w2 = wb4[i + 2048];
        float4 w3 = wb4[i + 3072];
        ulonglong2 a01 = shp[i];            // pos 4i (.x), 4i+1 (.y) batches 0,1
        ulonglong2 b01 = shp[i + 1024];     // pos 4i+2, 4i+3
        ulonglong2 a23 = shp[i + 2048];
        ulonglong2 b23 = shp[i + 3072];

        const float4 wv_[4] = {w0, w1, w2, w3};
        #pragma unroll
        for (int r = 0; r < 4; r++) {
            unsigned long long p;
            p = pack2(wv_[r].x); fma2(acc01[r], p, a01.x); fma2(acc23[r], p, a23.x);
            p = pack2(wv_[r].y); fma2(acc01[r], p, a01.y); fma2(acc23[r], p, a23.y);
            p = pack2(wv_[r].z); fma2(acc01[r], p, b01.x); fma2(acc23[r], p, b23.x);
            p = pack2(wv_[r].w); fma2(acc01[r], p, b01.y); fma2(acc23[r], p, b23.y);
        }
    }

    float acc[4][BB];
    #pragma unroll
    for (int r = 0; r < 4; r++) {
        unpack2(acc01[r], acc[r][0], acc[r][1]);
        unpack2(acc23[r], acc[r][2], acc[r][3]);
    }

    #pragma unroll
    for (int off = 16; off > 0; off >>= 1)
        #pragma unroll
        for (int r = 0; r < 4; r++)
            #pragma unroll
            for (int b = 0; b < BB; b++)
                acc[r][b] += __shfl_down_sync(0xffffffffu, acc[r][b], off);

    if (lane == 0) {
        const int n  = r0 >> 7;             // kv head
        const int m0 = (r0 & 127) >> 1;     // first rope-pair index
        const long long base_t = (kv == 0) ? 0LL : TEN;
        #pragma unroll
        for (int p = 0; p < 2; p++) {
            const float f = inv_freq[l * (HD / 2) + m0 + p];
            #pragma unroll
            for (int b = 0; b < BB; b++) {
                float e = acc[2 * p][b];
                float o = acc[2 * p + 1][b];
                float re = e, ro = o;
                if (kv == 0) {
                    float ang = (float)pos_id[b] * f;
                    float s, c;
                    sincosf(ang, &s, &c);
                    re = e * c - o * s;
                    ro = e * s + o * c;
                }
                long long dst = base_t +
                    ((((long long)l * BB + b) * NKVH + n) * (SS + 1) + SS) * HD
                    + 2 * (m0 + p);
                out[dst]     = re;
                out[dst + 1] = ro;
            }
        }
    }
}

extern "C" void kernel_launch(void* const* d_in, const int* in_sizes, int n_in,
                              void* d_out, int out_size) {
    const int*   token_id = (const int*)d_in[0];
    const int*   pos_id   = (const int*)d_in[1];
    const float* embed_w  = (const float*)d_in[2];
    // d_in[3] = wq (unused: q never escapes the reference)
    const float* wk       = (const float*)d_in[4];
    const float* wv       = (const float*)d_in[5];
    const float* inv_freq = (const float*)d_in[6];
    const float* past_k   = (const float*)d_in[7];
    const float* past_v   = (const float*)d_in[8];
    float*       out      = (float*)d_out;

    cudaFuncSetAttribute(kv_fused_kernel,
                         cudaFuncAttributeMaxDynamicSharedMemorySize, 65536);

    kv_fused_kernel<<<NBLOCKS, NTHREADS, 65536>>>(
        token_id, pos_id, embed_w, wk, wv, inv_freq,
        (const float4*)past_k, (const float4*)past_v, out);
}